// round 5
// baseline (speedup 1.0000x reference)
#include <cuda_runtime.h>
#include <math.h>

#define PI_F 3.14159265358979323846f

// Problem constants
#define B_  8
#define C_  3
#define NF_ 2
#define H0_ 512
#define W0_ 1024

// Pyramid scratch (levels 1..3) for ref, tgt0, tgt1. Layout per image:
// [L1: B*C*256*512][L2: B*C*128*256][L3: B*C*64*128]
#define L1_N (B_*C_*256*512)   /* 3145728 */
#define L2_N (B_*C_*128*256)   /*  786432 */
#define L3_N (B_*C_*64*128)    /*  196608 */
#define L1_OFF 0
#define L2_OFF (L1_N)
#define L3_OFF (L1_N + L2_N)
#define PYR_N  (L1_N + L2_N + L3_N)

__device__ float g_pyr_ref[PYR_N];
__device__ float g_pyr_t0[PYR_N];
__device__ float g_pyr_t1[PYR_N];
__device__ float g_R[B_ * NF_ * 9];
__device__ float g_t[B_ * NF_ * 3];
__device__ double g_acc;

// ---------------------------------------------------------------------------
// init: zero accumulator, compute Rodrigues R and t for all (b, n) pairs
// ---------------------------------------------------------------------------
__global__ void init_kernel(const float* __restrict__ pose) {
    int i = threadIdx.x;
    if (i == 0) g_acc = 0.0;
    if (i < B_ * NF_) {
        const float* p = pose + i * 6;
        float tx = p[0], ty = p[1], tz = p[2];
        float rx = p[3], ry = p[4], rz = p[5];
        float th  = sqrtf(rx * rx + ry * ry + rz * rz);
        float inv = 1.0f / fmaxf(th, 1e-8f);
        float kx = rx * inv, ky = ry * inv, kz = rz * inv;
        float s = sinf(th), c = cosf(th);
        float oc = 1.0f - c;
        float R[9];
        // R = I + s*K + oc*K^2,  K = [[0,-kz,ky],[kz,0,-kx],[-ky,kx,0]]
        R[0] = 1.0f + oc * (-(ky * ky + kz * kz));
        R[1] = -s * kz + oc * (kx * ky);
        R[2] =  s * ky + oc * (kx * kz);
        R[3] =  s * kz + oc * (kx * ky);
        R[4] = 1.0f + oc * (-(kx * kx + kz * kz));
        R[5] = -s * kx + oc * (ky * kz);
        R[6] = -s * ky + oc * (kx * kz);
        R[7] =  s * kx + oc * (ky * kz);
        R[8] = 1.0f + oc * (-(kx * kx + ky * ky));
#pragma unroll
        for (int k = 0; k < 9; k++) g_R[i * 9 + k] = R[k];
        g_t[i * 3 + 0] = tx; g_t[i * 3 + 1] = ty; g_t[i * 3 + 2] = tz;
    }
}

// ---------------------------------------------------------------------------
// 2x2 area downsample: dst (B,C,h2,w2) from src (B,C,2h2,2w2)
// float2 loads: x*2 is even, so each row-pair is one aligned 64-bit load.
// ---------------------------------------------------------------------------
__global__ void ds2_kernel(const float* __restrict__ src, float* __restrict__ dst,
                           int h2, int w2, int n) {
    int i = blockIdx.x * blockDim.x + threadIdx.x;
    if (i >= n) return;
    int x  = i % w2;
    int y  = (i / w2) % h2;
    int bc = i / (w2 * h2);
    int ws = w2 * 2;
    const float* s = src + ((size_t)bc * (h2 * 2) + y * 2) * ws + x * 2;
    float2 a = *(const float2*)s;
    float2 b = *(const float2*)(s + ws);
    dst[i] = 0.25f * ((a.x + a.y) + (b.x + b.y));
}

// ---------------------------------------------------------------------------
// Main loss kernel for one scale: both frames, all channels.
// ---------------------------------------------------------------------------
__global__ void loss_kernel(const float* __restrict__ depth,
                            const float* __restrict__ mask,
                            const float* __restrict__ rr,
                            const float* __restrict__ tg0,
                            const float* __restrict__ tg1,
                            int h, int w, float invN) {
    int idx = blockIdx.x * blockDim.x + threadIdx.x;
    int HW  = h * w;
    float acc = 0.0f;

    if (idx < B_ * HW) {
        int x = idx % w;
        int y = (idx / w) % h;
        int b = idx / HW;

        // equirectangular direction
        float lon = ((x + 0.5f) / (float)w * 2.0f - 1.0f) * PI_F;
        float lat = -((y + 0.5f) / (float)h * 2.0f - 1.0f) * (0.5f * PI_F);
        float clat = cosf(lat), slat = sinf(lat);
        float clon = cosf(lon), slon = sinf(lon);

        float d = depth[idx];                 // (B,1,h,w) == linear idx
        float px0 = d * clat * slon;
        float py0 = d * slat;
        float pz0 = d * clat * clon;

        size_t rbase = (size_t)b * C_ * HW + (size_t)y * w + x;
        float r0 = rr[rbase];
        float r1 = rr[rbase + HW];
        float r2 = rr[rbase + 2 * HW];

#pragma unroll
        for (int n = 0; n < NF_; n++) {
            const float* Rp = &g_R[(b * NF_ + n) * 9];
            const float* Tp = &g_t[(b * NF_ + n) * 3];
            float px = Rp[0] * px0 + Rp[1] * py0 + Rp[2] * pz0 + Tp[0];
            float py = Rp[3] * px0 + Rp[4] * py0 + Rp[5] * pz0 + Tp[1];
            float pz = Rp[6] * px0 + Rp[7] * py0 + Rp[8] * pz0 + Tp[2];

            float nrm  = sqrtf(px * px + py * py + pz * pz);
            float lon2 = atan2f(px, pz);
            float sv   = py / fmaxf(nrm, 1e-8f);
            sv = fminf(fmaxf(sv, -1.0f), 1.0f);
            float lat2 = asinf(sv);

            float X = lon2 * (1.0f / PI_F);
            float Y = lat2 * (2.0f / PI_F);
            float fx = (X + 1.0f) * 0.5f * (float)(w - 1);
            float fy = (Y + 1.0f) * 0.5f * (float)(h - 1);
            float x0f = floorf(fx), y0f = floorf(fy);
            float x1f = x0f + 1.0f, y1f = y0f + 1.0f;

            float wa = (x1f - fx) * (y1f - fy);
            float wb = (x1f - fx) * (fy - y0f);
            float wc = (fx - x0f) * (y1f - fy);
            float wd = (fx - x0f) * (fy - y0f);

            bool vx0 = (x0f >= 0.0f) && (x0f <= (float)(w - 1));
            bool vx1 = (x1f >= 0.0f) && (x1f <= (float)(w - 1));
            bool vy0 = (y0f >= 0.0f) && (y0f <= (float)(h - 1));
            bool vy1 = (y1f >= 0.0f) && (y1f <= (float)(h - 1));

            int xi = (int)x0f;
            int yi = (int)y0f;

            const float* tg = (n == 0) ? tg0 : tg1;
            const float* tb = tg + (size_t)b * C_ * HW;

            float m = mask[(((size_t)b * NF_ + n) * h + y) * w + x];

            // Gather all 12 taps (3 channels x 4 taps) with loads grouped for MLP.
            float ta[C_], tbv[C_], tcv[C_], tdv[C_];
#pragma unroll
            for (int c = 0; c < C_; c++) {
                const float* tc = tb + (size_t)c * HW;
                ta[c]  = (vx0 && vy0) ? __ldg(&tc[(size_t)yi * w + xi])           : 0.0f;
                tbv[c] = (vx0 && vy1) ? __ldg(&tc[(size_t)(yi + 1) * w + xi])     : 0.0f;
                tcv[c] = (vx1 && vy0) ? __ldg(&tc[(size_t)yi * w + xi + 1])       : 0.0f;
                tdv[c] = (vx1 && vy1) ? __ldg(&tc[(size_t)(yi + 1) * w + xi + 1]) : 0.0f;
            }
            float s3 = 0.0f;
#pragma unroll
            for (int c = 0; c < C_; c++) {
                float v = wa * ta[c] + wb * tbv[c] + wc * tcv[c] + wd * tdv[c];
                float r = (c == 0) ? r0 : ((c == 1) ? r1 : r2);
                s3 += fabsf(r - v);
            }
            acc += m * s3;
        }
        acc *= invN;
    }

    // block reduction -> one double atomic per block
#pragma unroll
    for (int o = 16; o > 0; o >>= 1)
        acc += __shfl_down_sync(0xffffffffu, acc, o);
    __shared__ float ssum[8];
    int lane = threadIdx.x & 31, warp = threadIdx.x >> 5;
    if (lane == 0) ssum[warp] = acc;
    __syncthreads();
    if (warp == 0) {
        float v = (lane < (int)(blockDim.x >> 5)) ? ssum[lane] : 0.0f;
#pragma unroll
        for (int o = 4; o > 0; o >>= 1)
            v += __shfl_down_sync(0xffu, v, o);
        if (lane == 0) atomicAdd(&g_acc, (double)v);
    }
}

__global__ void finish_kernel(float* out) { out[0] = (float)g_acc; }

// ---------------------------------------------------------------------------
extern "C" void kernel_launch(void* const* d_in, const int* in_sizes, int n_in,
                              void* d_out, int out_size) {
    // Classify inputs by element count (all distinct), robust to metadata order.
    // ref/tgt rgb: 12582912 (order of appearance: ref, tgt0, tgt1)
    // depth_i: 8*h*w   = 4194304, 1048576, 262144, 65536
    // mask_i:  16*h*w  = 8388608, 2097152, 524288, 131072
    // pose: 96
    const float* ref = 0; const float* t0 = 0; const float* t1 = 0;
    const float* dep[4] = {0,0,0,0};
    const float* msk[4] = {0,0,0,0};
    const float* pose = 0;
    int rgb_seen = 0;
    for (int i = 0; i < n_in; i++) {
        const float* p = (const float*)d_in[i];
        switch (in_sizes[i]) {
            case 12582912: { if (rgb_seen == 0) ref = p; else if (rgb_seen == 1) t0 = p; else t1 = p; rgb_seen++; } break;
            case 4194304: dep[0] = p; break;
            case 1048576: dep[1] = p; break;
            case  262144: dep[2] = p; break;
            case   65536: dep[3] = p; break;
            case 8388608: msk[0] = p; break;
            case 2097152: msk[1] = p; break;
            case  524288: msk[2] = p; break;
            case  131072: msk[3] = p; break;
            case      96: pose = p; break;
            default: break;
        }
    }

    float *pr, *p0, *p1;
    cudaGetSymbolAddress((void**)&pr, g_pyr_ref);
    cudaGetSymbolAddress((void**)&p0, g_pyr_t0);
    cudaGetSymbolAddress((void**)&p1, g_pyr_t1);

    init_kernel<<<1, 32>>>(pose);

    const int TB = 256;
    // Build pyramids (level k from level k-1; 2x2 means compose to area means)
    const float* srcs[3] = { ref, t0, t1 };
    float* bases[3] = { pr, p0, p1 };
    for (int im = 0; im < 3; im++) {
        int n1 = L1_N;
        ds2_kernel<<<(n1 + TB - 1) / TB, TB>>>(srcs[im], bases[im] + L1_OFF, 256, 512, n1);
        int n2 = L2_N;
        ds2_kernel<<<(n2 + TB - 1) / TB, TB>>>(bases[im] + L1_OFF, bases[im] + L2_OFF, 128, 256, n2);
        int n3 = L3_N;
        ds2_kernel<<<(n3 + TB - 1) / TB, TB>>>(bases[im] + L2_OFF, bases[im] + L3_OFF, 64, 128, n3);
    }

    // Per-scale loss
    struct Sc { const float* rr; const float* g0; const float* g1; int h, w; };
    Sc sc[4] = {
        { ref,          t0,           t1,           512, 1024 },
        { pr + L1_OFF,  p0 + L1_OFF,  p1 + L1_OFF,  256,  512 },
        { pr + L2_OFF,  p0 + L2_OFF,  p1 + L2_OFF,  128,  256 },
        { pr + L3_OFF,  p0 + L3_OFF,  p1 + L3_OFF,   64,  128 },
    };
    for (int i = 0; i < 4; i++) {
        int h = sc[i].h, w = sc[i].w;
        int n = B_ * h * w;
        float invN = 1.0f / (float)(B_ * C_ * h * w);
        loss_kernel<<<(n + TB - 1) / TB, TB>>>(dep[i], msk[i], sc[i].rr,
                                               sc[i].g0, sc[i].g1, h, w, invN);
    }

    finish_kernel<<<1, 1>>>((float*)d_out);
}

// round 7
// speedup vs baseline: 1.2573x; 1.2573x over previous
#include <cuda_runtime.h>
#include <math.h>

#define PI_F 3.14159265358979323846f

#define B_  8
#define C_  3
#define NF_ 2

// Pyramid scratch (levels 1..3), per image, laid out (B,C,h,w) contiguous.
#define L1_N (B_*C_*256*512)
#define L2_N (B_*C_*128*256)
#define L3_N (B_*C_*64*128)
#define L1_OFF 0
#define L2_OFF (L1_N)
#define L3_OFF (L1_N + L2_N)
#define PYR_N  (L1_N + L2_N + L3_N)

__device__ float  g_pyr_ref[PYR_N];
__device__ float  g_pyr_t0[PYR_N];
__device__ float  g_pyr_t1[PYR_N];
__device__ float  g_R[B_ * NF_ * 9];
__device__ float  g_t[B_ * NF_ * 3];
__device__ double g_acc;
// Trig LUTs. lat: (cos,sin), offsets per scale {0,512,768,896}, total 960.
// lon: (sin,cos), offsets per scale {0,1024,1536,1792}, total 1920.
__device__ float2 g_lat[960];
__device__ float2 g_lon[1920];

// ---------------------------------------------------------------------------
// init: LUTs + Rodrigues + zero accumulator. grid 12x256 covers 2897 ids.
// ---------------------------------------------------------------------------
__global__ void init_kernel(const float* __restrict__ pose) {
    int idx = blockIdx.x * blockDim.x + threadIdx.x;
    if (idx < 960) {
        int s, y0;
        if (idx < 512)      { s = 0; y0 = 0;   }
        else if (idx < 768) { s = 1; y0 = 512; }
        else if (idx < 896) { s = 2; y0 = 768; }
        else                { s = 3; y0 = 896; }
        int h = 512 >> s;
        int y = idx - y0;
        float lat = -(((y + 0.5f) / (float)h) * 2.0f - 1.0f) * (0.5f * PI_F);
        g_lat[idx] = make_float2(cosf(lat), sinf(lat));
    } else if (idx < 2880) {
        int i2 = idx - 960;
        int s, x0;
        if (i2 < 1024)      { s = 0; x0 = 0;    }
        else if (i2 < 1536) { s = 1; x0 = 1024; }
        else if (i2 < 1792) { s = 2; x0 = 1536; }
        else                { s = 3; x0 = 1792; }
        int w = 1024 >> s;
        int x = i2 - x0;
        float lon = (((x + 0.5f) / (float)w) * 2.0f - 1.0f) * PI_F;
        g_lon[i2] = make_float2(sinf(lon), cosf(lon));
    } else if (idx < 2896) {
        int i = idx - 2880;
        const float* p = pose + i * 6;
        float rx = p[3], ry = p[4], rz = p[5];
        float th  = sqrtf(rx * rx + ry * ry + rz * rz);
        float inv = 1.0f / fmaxf(th, 1e-8f);
        float kx = rx * inv, ky = ry * inv, kz = rz * inv;
        float s = sinf(th), c = cosf(th);
        float oc = 1.0f - c;
        float R[9];
        R[0] = 1.0f + oc * (-(ky * ky + kz * kz));
        R[1] = -s * kz + oc * (kx * ky);
        R[2] =  s * ky + oc * (kx * kz);
        R[3] =  s * kz + oc * (kx * ky);
        R[4] = 1.0f + oc * (-(kx * kx + kz * kz));
        R[5] = -s * kx + oc * (ky * kz);
        R[6] = -s * ky + oc * (kx * kz);
        R[7] =  s * kx + oc * (ky * kz);
        R[8] = 1.0f + oc * (-(kx * kx + ky * ky));
#pragma unroll
        for (int k = 0; k < 9; k++) g_R[i * 9 + k] = R[k];
        g_t[i * 3 + 0] = p[0]; g_t[i * 3 + 1] = p[1]; g_t[i * 3 + 2] = p[2];
    } else if (idx == 2896) {
        g_acc = 0.0;
    }
}

// ---------------------------------------------------------------------------
// Per-pixel loss (shared by both loss kernels). Dims are powers of two:
// lw/lh = log2(w)/log2(h).
// ---------------------------------------------------------------------------
__device__ __forceinline__ float loss_pixel(
    const float* __restrict__ dep, const float* __restrict__ msk,
    const float* __restrict__ rr,  const float* __restrict__ tg0,
    const float* __restrict__ tg1,
    int lw, int lh, const float2* __restrict__ latL,
    const float2* __restrict__ lonL, int idx)
{
    int w  = 1 << lw, h = 1 << lh;
    int HW = w * h;
    int x = idx & (w - 1);
    int y = (idx >> lw) & (h - 1);
    int b = idx >> (lw + lh);

    float2 lt = latL[y];   // (clat, slat)
    float2 ln = lonL[x];   // (slon, clon)
    float d = dep[idx];
    float px0 = d * lt.x * ln.x;
    float py0 = d * lt.y;
    float pz0 = d * lt.x * ln.y;

    size_t rbase = (size_t)b * C_ * HW + (size_t)y * w + x;
    float r0 = rr[rbase];
    float r1 = rr[rbase + HW];
    float r2 = rr[rbase + 2 * HW];

    float acc = 0.0f;
#pragma unroll
    for (int n = 0; n < NF_; n++) {
        const float* Rp = &g_R[(b * NF_ + n) * 9];
        const float* Tp = &g_t[(b * NF_ + n) * 3];
        float px = Rp[0] * px0 + Rp[1] * py0 + Rp[2] * pz0 + Tp[0];
        float py = Rp[3] * px0 + Rp[4] * py0 + Rp[5] * pz0 + Tp[1];
        float pz = Rp[6] * px0 + Rp[7] * py0 + Rp[8] * pz0 + Tp[2];

        float n2 = fmaxf(px * px + py * py + pz * pz, 1e-16f);
        float sv = py * rsqrtf(n2);
        sv = fminf(fmaxf(sv, -1.0f), 1.0f);
        float lon2 = atan2f(px, pz);
        float lat2 = asinf(sv);

        float fx = (lon2 * (1.0f / PI_F) + 1.0f) * 0.5f * (float)(w - 1);
        float fy = (lat2 * (2.0f / PI_F) + 1.0f) * 0.5f * (float)(h - 1);
        float x0f = floorf(fx), y0f = floorf(fy);
        float x1f = x0f + 1.0f, y1f = y0f + 1.0f;

        float wa = (x1f - fx) * (y1f - fy);
        float wb = (x1f - fx) * (fy - y0f);
        float wc = (fx - x0f) * (y1f - fy);
        float wd = (fx - x0f) * (fy - y0f);

        bool vx0 = (x0f >= 0.0f) && (x0f <= (float)(w - 1));
        bool vx1 = (x1f >= 0.0f) && (x1f <= (float)(w - 1));
        bool vy0 = (y0f >= 0.0f) && (y0f <= (float)(h - 1));
        bool vy1 = (y1f >= 0.0f) && (y1f <= (float)(h - 1));

        int xi = (int)x0f;
        int yi = (int)y0f;

        const float* tb = ((n == 0) ? tg0 : tg1) + (size_t)b * C_ * HW;
        float m = msk[(((size_t)b * NF_ + n) << (lw + lh)) + ((size_t)y << lw) + x];

        float ta[C_], tbv[C_], tcv[C_], tdv[C_];
#pragma unroll
        for (int c = 0; c < C_; c++) {
            const float* tc = tb + (size_t)c * HW;
            ta[c]  = (vx0 && vy0) ? __ldg(&tc[(size_t)yi * w + xi])           : 0.0f;
            tbv[c] = (vx0 && vy1) ? __ldg(&tc[(size_t)(yi + 1) * w + xi])     : 0.0f;
            tcv[c] = (vx1 && vy0) ? __ldg(&tc[(size_t)yi * w + xi + 1])       : 0.0f;
            tdv[c] = (vx1 && vy1) ? __ldg(&tc[(size_t)(yi + 1) * w + xi + 1]) : 0.0f;
        }
        float s3 = 0.0f;
#pragma unroll
        for (int c = 0; c < C_; c++) {
            float v = wa * ta[c] + wb * tbv[c] + wc * tcv[c] + wd * tdv[c];
            float r = (c == 0) ? r0 : ((c == 1) ? r1 : r2);
            s3 += fabsf(r - v);
        }
        acc += m * s3;
    }
    return acc;
}

__device__ __forceinline__ void block_reduce_add(float acc) {
#pragma unroll
    for (int o = 16; o > 0; o >>= 1)
        acc += __shfl_down_sync(0xffffffffu, acc, o);
    __shared__ float ssum[8];
    int lane = threadIdx.x & 31, warp = threadIdx.x >> 5;
    if (lane == 0) ssum[warp] = acc;
    __syncthreads();
    if (warp == 0) {
        float v = (lane < 8) ? ssum[lane] : 0.0f;
#pragma unroll
        for (int o = 4; o > 0; o >>= 1)
            v += __shfl_down_sync(0xffu, v, o);
        if (lane == 0) atomicAdd(&g_acc, (double)v);
    }
}

// ---------------------------------------------------------------------------
// Mega kernel: blocks [0, 9216) = tiled pyramid build (3 imgs x 24 planes x
// 128 tiles of 64x64); blocks [9216, 25600) = scale-0 loss (independent of
// the pyramid, reads only original inputs).
// ---------------------------------------------------------------------------
#define PYRB 9216
#define INV0 (1.0f / (float)(B_ * C_ * 512 * 1024))

__global__ __launch_bounds__(256) void mega_kernel(
    const float* __restrict__ ref, const float* __restrict__ t0,
    const float* __restrict__ t1,
    const float* __restrict__ dep0, const float* __restrict__ msk0)
{
    int blk = blockIdx.x;
    int tid = threadIdx.x;
    if (blk < PYRB) {
        __shared__ float s1[1024];
        __shared__ float s2[256];
        int tile  = blk & 127;
        int plane = blk >> 7;          // 0..71
        int img   = plane / 24;
        int bc    = plane % 24;
        int tx = tile & 15, ty = tile >> 4;
        const float* src = (img == 0 ? ref : (img == 1 ? t0 : t1)) + (size_t)bc * 512 * 1024;
        float* pyr = (img == 0 ? g_pyr_ref : (img == 1 ? g_pyr_t0 : g_pyr_t1));
        float* d1 = pyr + L1_OFF + (size_t)bc * 256 * 512;
        float* d2 = pyr + L2_OFF + (size_t)bc * 128 * 256;
        float* d3 = pyr + L3_OFF + (size_t)bc * 64 * 128;
#pragma unroll
        for (int k = 0; k < 4; k++) {
            int i  = tid + k * 256;
            int lx = i & 31, ly = i >> 5;
            int gy = ty * 64 + ly * 2, gx = tx * 64 + lx * 2;
            float2 a = *(const float2*)(src + (size_t)gy * 1024 + gx);
            float2 b = *(const float2*)(src + (size_t)(gy + 1) * 1024 + gx);
            float v = 0.25f * ((a.x + a.y) + (b.x + b.y));
            s1[i] = v;
            d1[(size_t)(ty * 32 + ly) * 512 + tx * 32 + lx] = v;
        }
        __syncthreads();
        {
            int lx = tid & 15, ly = tid >> 4;
            float v = 0.25f * ((s1[(2 * ly) * 32 + 2 * lx] + s1[(2 * ly) * 32 + 2 * lx + 1]) +
                               (s1[(2 * ly + 1) * 32 + 2 * lx] + s1[(2 * ly + 1) * 32 + 2 * lx + 1]));
            s2[tid] = v;
            d2[(size_t)(ty * 16 + ly) * 256 + tx * 16 + lx] = v;
        }
        __syncthreads();
        if (tid < 64) {
            int lx = tid & 7, ly = tid >> 3;
            float v = 0.25f * ((s2[(2 * ly) * 16 + 2 * lx] + s2[(2 * ly) * 16 + 2 * lx + 1]) +
                               (s2[(2 * ly + 1) * 16 + 2 * lx] + s2[(2 * ly + 1) * 16 + 2 * lx + 1]));
            d3[(size_t)(ty * 8 + ly) * 128 + tx * 8 + lx] = v;
        }
    } else {
        int idx = (blk - PYRB) * 256 + tid;   // exactly 4194304 ids
        float acc = loss_pixel(dep0, msk0, ref, t0, t1,
                               10, 9, g_lat + 0, g_lon + 0, idx) * INV0;
        block_reduce_add(acc);
    }
}

// ---------------------------------------------------------------------------
// Loss for scales 1..3, fused by block range.
// blocks: [0,4096) s=1 (256x512), [4096,5120) s=2 (128x256), [5120,5376) s=3.
// ---------------------------------------------------------------------------
__global__ __launch_bounds__(256) void loss123_kernel(
    const float* __restrict__ dep1, const float* __restrict__ msk1,
    const float* __restrict__ dep2, const float* __restrict__ msk2,
    const float* __restrict__ dep3, const float* __restrict__ msk3)
{
    int blk = blockIdx.x;
    const float *dep, *msk;
    const float2 *latL, *lonL;
    int lw, lh, base;
    size_t off;
    float invN;
    if (blk < 4096) {
        dep = dep1; msk = msk1; lw = 9; lh = 8; base = 0;
        latL = g_lat + 512; lonL = g_lon + 1024; off = L1_OFF;
        invN = 1.0f / (float)(B_ * C_ * 256 * 512);
    } else if (blk < 5120) {
        dep = dep2; msk = msk2; lw = 8; lh = 7; base = 4096;
        latL = g_lat + 768; lonL = g_lon + 1536; off = L2_OFF;
        invN = 1.0f / (float)(B_ * C_ * 128 * 256);
    } else {
        dep = dep3; msk = msk3; lw = 7; lh = 6; base = 5120;
        latL = g_lat + 896; lonL = g_lon + 1792; off = L3_OFF;
        invN = 1.0f / (float)(B_ * C_ * 64 * 128);
    }
    int idx = (blk - base) * 256 + threadIdx.x;  // exact multiples; no bounds check
    float acc = loss_pixel(dep, msk, g_pyr_ref + off, g_pyr_t0 + off, g_pyr_t1 + off,
                           lw, lh, latL, lonL, idx) * invN;
    block_reduce_add(acc);
}

__global__ void finish_kernel(float* out) { out[0] = (float)g_acc; }

// ---------------------------------------------------------------------------
extern "C" void kernel_launch(void* const* d_in, const int* in_sizes, int n_in,
                              void* d_out, int out_size) {
    // Classify inputs by element count (robust to metadata ordering).
    const float* ref = 0; const float* t0 = 0; const float* t1 = 0;
    const float* dep[4] = {0,0,0,0};
    const float* msk[4] = {0,0,0,0};
    const float* pose = 0;
    int rgb_seen = 0;
    for (int i = 0; i < n_in; i++) {
        const float* p = (const float*)d_in[i];
        switch (in_sizes[i]) {
            case 12582912: { if (rgb_seen == 0) ref = p; else if (rgb_seen == 1) t0 = p; else t1 = p; rgb_seen++; } break;
            case 4194304: dep[0] = p; break;
            case 1048576: dep[1] = p; break;
            case  262144: dep[2] = p; break;
            case   65536: dep[3] = p; break;
            case 8388608: msk[0] = p; break;
            case 2097152: msk[1] = p; break;
            case  524288: msk[2] = p; break;
            case  131072: msk[3] = p; break;
            case      96: pose = p; break;
            default: break;
        }
    }

    init_kernel<<<12, 256>>>(pose);
    mega_kernel<<<PYRB + 16384, 256>>>(ref, t0, t1, dep[0], msk[0]);
    loss123_kernel<<<5376, 256>>>(dep[1], msk[1], dep[2], msk[2], dep[3], msk[3]);
    finish_kernel<<<1, 1>>>((float*)d_out);
}